// round 1
// baseline (speedup 1.0000x reference)
#include <cuda_runtime.h>
#include <math.h>

#define NN 10000
#define EE 160000
#define TT 12
#define LL 2
#define FF 256
#define K_FULL 1024
#define K_HALF 512
#define NOUT 512   // 2F (u|c)

// ---------------- device scratch (static globals; no allocation) ----------------
__device__ float g_in[NN * K_FULL];        // [x|ax|h|ah] packed rows (or [h|ah] stride 512)
__device__ float g_pre[NN * NOUT];         // GEMM output (u|c pre-activations)
__device__ float g_h0[NN * FF];            // layer 0 hidden
__device__ float g_h1[NN * FF];            // layer 1 hidden
__device__ float g_Wpack[4 * K_FULL * NOUT]; // enc0, enc1, dec0(half), dec1
__device__ float g_bias[4 * NOUT];
__device__ int   g_deg[NN];
__device__ int   g_rowptr[NN + 1];
__device__ int   g_cursor[NN];
__device__ int   g_col[EE];
__device__ float g_deginv[NN];

// ---------------- setup kernels ----------------
__global__ void k_zero_int(int* p, int n) {
    int i = blockIdx.x * blockDim.x + threadIdx.x;
    if (i < n) p[i] = 0;
}
__global__ void k_zero_f(float* p, int n) {
    int i = blockIdx.x * blockDim.x + threadIdx.x;
    if (i < n) p[i] = 0.0f;
}
__global__ void k_count_deg(const int* __restrict__ dst) {
    int e = blockIdx.x * blockDim.x + threadIdx.x;
    if (e < EE) atomicAdd(&g_deg[dst[e]], 1);
}
// single-block scan over N=10000
__global__ void k_scan_deg() {
    __shared__ int partial[256];
    int t = threadIdx.x;
    const int CH = (NN + 255) / 256;
    int base = t * CH;
    int s = 0;
    for (int i = 0; i < CH; i++) {
        int idx = base + i;
        if (idx < NN) s += g_deg[idx];
    }
    partial[t] = s;
    __syncthreads();
    if (t == 0) {
        int run = 0;
        for (int i = 0; i < 256; i++) { int v = partial[i]; partial[i] = run; run += v; }
        g_rowptr[NN] = run;
    }
    __syncthreads();
    int run = partial[t];
    for (int i = 0; i < CH; i++) {
        int idx = base + i;
        if (idx < NN) {
            g_rowptr[idx] = run;
            g_cursor[idx] = run;
            int d = g_deg[idx];
            g_deginv[idx] = (d > 0) ? (1.0f / (float)d) : 0.0f;
            run += d;
        }
    }
}
__global__ void k_fill_csr(const int* __restrict__ src, const int* __restrict__ dst) {
    int e = blockIdx.x * blockDim.x + threadIdx.x;
    if (e < EE) {
        int p = atomicAdd(&g_cursor[dst[e]], 1);
        g_col[p] = src[e];
    }
}

// pack weights: keep only output cols F..3F; rows stacked [Wxs;Wxn;Whs;Whn] (full) or [Whs;Whn] (half)
__global__ void k_pack_w(const float* __restrict__ Wxs, const float* __restrict__ Wxn,
                         const float* __restrict__ Whs, const float* __restrict__ Whn,
                         const float* __restrict__ bx, const float* __restrict__ bh,
                         float* __restrict__ Wout, float* __restrict__ bout, int full) {
    int K = full ? K_FULL : K_HALF;
    int j = blockIdx.x * blockDim.x + threadIdx.x;
    if (j >= K * NOUT) return;
    int k = j / NOUT, n = j % NOUT;
    int r = k & (FF - 1);
    int blk = k >> 8;
    const float* srcW;
    if (full) srcW = (blk == 0) ? Wxs : (blk == 1) ? Wxn : (blk == 2) ? Whs : Whn;
    else      srcW = (blk == 0) ? Whs : Whn;
    Wout[j] = srcW[r * (3 * FF) + FF + n];
    if (k == 0) bout[n] = bx[FF + n] + bh[FF + n];
}

// ---------------- aggregation + input build ----------------
// full: in[node] = [ x(node) | mean_nbr x | h(node) | mean_nbr h ]  (stride 1024)
__global__ void k_agg_full(const float* __restrict__ xsrc, const float* __restrict__ h) {
    int node = blockIdx.x;
    int f = threadIdx.x;  // 256
    int beg = g_rowptr[node], end = g_rowptr[node + 1];
    float sx = 0.f, sh = 0.f;
    for (int j = beg; j < end; j++) {
        int s = g_col[j];
        sx += xsrc[s * FF + f];
        sh += h[s * FF + f];
    }
    float di = g_deginv[node];
    int base = node * K_FULL;
    g_in[base + f]            = xsrc[node * FF + f];
    g_in[base + 256 + f]      = sx * di;
    g_in[base + 512 + f]      = h[node * FF + f];
    g_in[base + 768 + f]      = sh * di;
}
// half (decoder L0, x==0): in[node] = [ h(node) | mean_nbr h ]  (stride 512)
__global__ void k_agg_half(const float* __restrict__ h) {
    int node = blockIdx.x;
    int f = threadIdx.x;
    int beg = g_rowptr[node], end = g_rowptr[node + 1];
    float sh = 0.f;
    for (int j = beg; j < end; j++) sh += h[g_col[j] * FF + f];
    int base = node * K_HALF;
    g_in[base + f]       = h[node * FF + f];
    g_in[base + 256 + f] = sh * g_deginv[node];
}

// ---------------- SGEMM: C[M,Nn] = A[M,K] @ B[K,Nn] + bias ----------------
#define BM 128
#define BN 128
#define BK 16
__global__ __launch_bounds__(256) void k_sgemm_bias(
    const float* __restrict__ A, int lda,
    const float* __restrict__ B, int ldb,
    const float* __restrict__ bias,
    float* __restrict__ C, int ldc,
    int M, int Nn, int K) {
    __shared__ float As[BK][BM + 4];
    __shared__ float Bs[BK][BN];
    int tid = threadIdx.x;
    int bm = blockIdx.y * BM, bn = blockIdx.x * BN;
    int tr = tid >> 4, tc = tid & 15;   // 16x16 thread grid
    int arow = tid >> 2;                // 0..63
    int acol = (tid & 3) << 2;          // 0,4,8,12
    int brow = tid >> 5;                // 0..7
    int bcol = (tid & 31) << 2;

    float acc[8][8];
#pragma unroll
    for (int i = 0; i < 8; i++)
#pragma unroll
        for (int j = 0; j < 8; j++) acc[i][j] = 0.0f;

    for (int k0 = 0; k0 < K; k0 += BK) {
#pragma unroll
        for (int i = 0; i < 2; i++) {
            int r = arow + i * 64;
            int gm = bm + r;
            float4 v = make_float4(0.f, 0.f, 0.f, 0.f);
            if (gm < M) v = *(const float4*)&A[gm * lda + k0 + acol];
            As[acol + 0][r] = v.x;
            As[acol + 1][r] = v.y;
            As[acol + 2][r] = v.z;
            As[acol + 3][r] = v.w;
        }
#pragma unroll
        for (int i = 0; i < 2; i++) {
            int r = brow + i * 8;
            *(float4*)&Bs[r][bcol] = *(const float4*)&B[(k0 + r) * ldb + bn + bcol];
        }
        __syncthreads();
#pragma unroll
        for (int kk = 0; kk < BK; kk++) {
            float4 a0 = *(const float4*)&As[kk][tr * 4];
            float4 a1 = *(const float4*)&As[kk][64 + tr * 4];
            float4 b0 = *(const float4*)&Bs[kk][tc * 4];
            float4 b1 = *(const float4*)&Bs[kk][64 + tc * 4];
            float a[8] = {a0.x, a0.y, a0.z, a0.w, a1.x, a1.y, a1.z, a1.w};
            float b[8] = {b0.x, b0.y, b0.z, b0.w, b1.x, b1.y, b1.z, b1.w};
#pragma unroll
            for (int i = 0; i < 8; i++)
#pragma unroll
                for (int j = 0; j < 8; j++) acc[i][j] += a[i] * b[j];
        }
        __syncthreads();
    }
    // epilogue with bias
    float bb[8];
#pragma unroll
    for (int j = 0; j < 4; j++) bb[j] = bias[bn + tc * 4 + j];
#pragma unroll
    for (int j = 0; j < 4; j++) bb[4 + j] = bias[bn + 64 + tc * 4 + j];
#pragma unroll
    for (int i = 0; i < 8; i++) {
        int r = (i < 4) ? (tr * 4 + i) : (64 + tr * 4 + i - 4);
        int gm = bm + r;
        if (gm < M) {
            float4 v0 = make_float4(acc[i][0] + bb[0], acc[i][1] + bb[1],
                                    acc[i][2] + bb[2], acc[i][3] + bb[3]);
            float4 v1 = make_float4(acc[i][4] + bb[4], acc[i][5] + bb[5],
                                    acc[i][6] + bb[6], acc[i][7] + bb[7]);
            *(float4*)&C[gm * ldc + bn + tc * 4] = v0;
            *(float4*)&C[gm * ldc + bn + 64 + tc * 4] = v1;
        }
    }
}

// ---------------- GRU pointwise update: h = u*h + (1-u)*c ----------------
__global__ void k_gru_update(float* __restrict__ h) {
    int idx = blockIdx.x * blockDim.x + threadIdx.x;
    if (idx >= NN * FF) return;
    int n = idx >> 8, f = idx & (FF - 1);
    float zu = g_pre[n * NOUT + f];
    float zc = g_pre[n * NOUT + 256 + f];
    float u = 1.0f / (1.0f + expf(-zu));
    float c = tanhf(zc);
    float hv = h[idx];
    h[idx] = u * hv + (1.0f - u) * c;
}

// ---------------- host orchestration ----------------
static inline float* dev_ptr_f(float* p) { return p; }

extern "C" void kernel_launch(void* const* d_in, const int* in_sizes, int n_in,
                              void* d_out, int out_size) {
    const float* x        = (const float*)d_in[0];
    const int*   src      = (const int*)d_in[1];
    const int*   dst      = (const int*)d_in[2];
    const float* eWxs     = (const float*)d_in[3];
    const float* eWxn     = (const float*)d_in[4];
    const float* ebx      = (const float*)d_in[5];
    const float* eWhs     = (const float*)d_in[6];
    const float* eWhn     = (const float*)d_in[7];
    const float* ebh      = (const float*)d_in[8];
    const float* dWxs     = (const float*)d_in[9];
    const float* dWxn     = (const float*)d_in[10];
    const float* dbx      = (const float*)d_in[11];
    const float* dWhs     = (const float*)d_in[12];
    const float* dWhn     = (const float*)d_in[13];
    const float* dbh      = (const float*)d_in[14];
    const float* outW     = (const float*)d_in[15];
    const float* outB     = (const float*)d_in[16];
    float* out = (float*)d_out;

    // resolve device-global addresses
    float *p_in, *p_pre, *p_h0, *p_h1, *p_Wpack, *p_bias, *p_deginv;
    int *p_deg;
    cudaGetSymbolAddress((void**)&p_in, g_in);
    cudaGetSymbolAddress((void**)&p_pre, g_pre);
    cudaGetSymbolAddress((void**)&p_h0, g_h0);
    cudaGetSymbolAddress((void**)&p_h1, g_h1);
    cudaGetSymbolAddress((void**)&p_Wpack, g_Wpack);
    cudaGetSymbolAddress((void**)&p_bias, g_bias);
    cudaGetSymbolAddress((void**)&p_deg, g_deg);
    cudaGetSymbolAddress((void**)&p_deginv, g_deginv);

    const int WLF = FF * 3 * FF;  // per-layer weight size
    const int BLF = 3 * FF;       // per-layer bias size

    // ---- graph structure ----
    k_zero_int<<<(NN + 255) / 256, 256>>>(p_deg, NN);
    k_count_deg<<<(EE + 255) / 256, 256>>>(dst);
    k_scan_deg<<<1, 256>>>();
    k_fill_csr<<<(EE + 255) / 256, 256>>>(src, dst);

    // ---- zero hidden state ----
    k_zero_f<<<(NN * FF + 255) / 256, 256>>>(p_h0, NN * FF);
    k_zero_f<<<(NN * FF + 255) / 256, 256>>>(p_h1, NN * FF);

    // ---- pack weights: 0=encL0, 1=encL1, 2=decL0(half), 3=decL1 ----
    {
        int nfull = K_FULL * NOUT, nhalf = K_HALF * NOUT;
        k_pack_w<<<(nfull + 255) / 256, 256>>>(eWxs, eWxn, eWhs, eWhn, ebx, ebh,
                                               p_Wpack + 0 * K_FULL * NOUT, p_bias + 0 * NOUT, 1);
        k_pack_w<<<(nfull + 255) / 256, 256>>>(eWxs + WLF, eWxn + WLF, eWhs + WLF, eWhn + WLF,
                                               ebx + BLF, ebh + BLF,
                                               p_Wpack + 1 * K_FULL * NOUT, p_bias + 1 * NOUT, 1);
        k_pack_w<<<(nhalf + 255) / 256, 256>>>(dWxs, dWxn, dWhs, dWhn, dbx, dbh,
                                               p_Wpack + 2 * K_FULL * NOUT, p_bias + 2 * NOUT, 0);
        k_pack_w<<<(nfull + 255) / 256, 256>>>(dWxs + WLF, dWxn + WLF, dWhs + WLF, dWhn + WLF,
                                               dbx + BLF, dbh + BLF,
                                               p_Wpack + 3 * K_FULL * NOUT, p_bias + 3 * NOUT, 1);
    }

    dim3 gemm_grid_pre(NOUT / BN, (NN + BM - 1) / BM);   // (4, 79)
    dim3 gemm_grid_out(FF / BN, (NN + BM - 1) / BM);     // (2, 79)
    int upd_grid = (NN * FF + 255) / 256;

    // ---- encoder ----
    for (int t = 0; t < TT; t++) {
        // layer 0: input = x[t], hidden = h0
        k_agg_full<<<NN, FF>>>(x + (size_t)t * NN * FF, p_h0);
        k_sgemm_bias<<<gemm_grid_pre, 256>>>(p_in, K_FULL,
                                             p_Wpack + 0 * K_FULL * NOUT, NOUT,
                                             p_bias + 0 * NOUT, p_pre, NOUT,
                                             NN, NOUT, K_FULL);
        k_gru_update<<<upd_grid, 256>>>(p_h0);
        // layer 1: input = new h0, hidden = h1
        k_agg_full<<<NN, FF>>>(p_h0, p_h1);
        k_sgemm_bias<<<gemm_grid_pre, 256>>>(p_in, K_FULL,
                                             p_Wpack + 1 * K_FULL * NOUT, NOUT,
                                             p_bias + 1 * NOUT, p_pre, NOUT,
                                             NN, NOUT, K_FULL);
        k_gru_update<<<upd_grid, 256>>>(p_h1);
    }

    // ---- decoder ----
    for (int t = 0; t < TT; t++) {
        // layer 0: input = zeros -> K=512 half path
        k_agg_half<<<NN, FF>>>(p_h0);
        k_sgemm_bias<<<gemm_grid_pre, 256>>>(p_in, K_HALF,
                                             p_Wpack + 2 * K_FULL * NOUT, NOUT,
                                             p_bias + 2 * NOUT, p_pre, NOUT,
                                             NN, NOUT, K_HALF);
        k_gru_update<<<upd_grid, 256>>>(p_h0);
        // layer 1: input = new h0, hidden = h1
        k_agg_full<<<NN, FF>>>(p_h0, p_h1);
        k_sgemm_bias<<<gemm_grid_pre, 256>>>(p_in, K_FULL,
                                             p_Wpack + 3 * K_FULL * NOUT, NOUT,
                                             p_bias + 3 * NOUT, p_pre, NOUT,
                                             NN, NOUT, K_FULL);
        k_gru_update<<<upd_grid, 256>>>(p_h1);
        // output projection: out[t] = h1 @ outW + outB
        k_sgemm_bias<<<gemm_grid_out, 256>>>(p_h1, FF,
                                             outW, FF,
                                             outB, out + (size_t)t * NN * FF, FF,
                                             NN, FF, FF);
    }
    (void)in_sizes; (void)n_in; (void)out_size;
}

// round 3
// speedup vs baseline: 1.7885x; 1.7885x over previous
#include <cuda_runtime.h>
#include <cuda_bf16.h>
#include <cstdint>
#include <math.h>

#define NN 10000
#define EE 160000
#define TT 12
#define FF 256
#define K_FULL 1024
#define K_HALF 512
#define NOUT 512

// ---------------- weight storage offsets (elements) ----------------
#define W_ENC0 0
#define W_ENC1 (512 * 1024)
#define W_DEC0 (2 * 512 * 1024)
#define W_DEC1 (2 * 512 * 1024 + 512 * 512)
#define W_OUTP (W_DEC1 + 512 * 1024)
#define W_TOTAL (W_OUTP + 256 * 256)

__device__ float         g_in[NN * K_FULL];
__device__ float         g_h0[NN * FF];
__device__ float         g_h1[NN * FF];
__device__ __nv_bfloat16 g_Wh[W_TOTAL];
__device__ __nv_bfloat16 g_Wl[W_TOTAL];
__device__ float         g_bias[4 * NOUT + FF];
__device__ int           g_deg[NN];
__device__ int           g_rowptr[NN + 1];
__device__ int           g_cursor[NN];
__device__ int           g_col[EE];
__device__ float         g_deginv[NN];

// ---------------- small helpers ----------------
__device__ __forceinline__ uint32_t smem_u32(const void* p) {
    uint32_t a;
    asm("{ .reg .u64 t; cvta.to.shared.u64 t, %1; cvt.u32.u64 %0, t; }" : "=r"(a) : "l"(p));
    return a;
}
__device__ __forceinline__ void ldsm_x4(uint32_t* r, uint32_t addr) {
    asm volatile("ldmatrix.sync.aligned.m8n8.x4.shared.b16 {%0,%1,%2,%3}, [%4];"
                 : "=r"(r[0]), "=r"(r[1]), "=r"(r[2]), "=r"(r[3]) : "r"(addr));
}
__device__ __forceinline__ void ldsm_x2(uint32_t* r, uint32_t addr) {
    asm volatile("ldmatrix.sync.aligned.m8n8.x2.shared.b16 {%0,%1}, [%2];"
                 : "=r"(r[0]), "=r"(r[1]) : "r"(addr));
}
__device__ __forceinline__ void mma_bf16(float* c, const uint32_t* a, const uint32_t* b) {
    asm volatile("mma.sync.aligned.m16n8k16.row.col.f32.bf16.bf16.f32 "
                 "{%0,%1,%2,%3}, {%4,%5,%6,%7}, {%8,%9}, {%0,%1,%2,%3};"
                 : "+f"(c[0]), "+f"(c[1]), "+f"(c[2]), "+f"(c[3])
                 : "r"(a[0]), "r"(a[1]), "r"(a[2]), "r"(a[3]), "r"(b[0]), "r"(b[1]));
}
__device__ __forceinline__ uint32_t pack_bf16_hi(float a, float b) {
    unsigned short ua = __bfloat16_as_ushort(__float2bfloat16_rn(a));
    unsigned short ub = __bfloat16_as_ushort(__float2bfloat16_rn(b));
    return (uint32_t)ua | ((uint32_t)ub << 16);
}

// ---------------- setup kernels ----------------
__global__ void k_zero_int(int* p, int n) {
    int i = blockIdx.x * blockDim.x + threadIdx.x;
    if (i < n) p[i] = 0;
}
__global__ void k_zero_f(float* p, int n) {
    int i = blockIdx.x * blockDim.x + threadIdx.x;
    if (i < n) p[i] = 0.0f;
}
__global__ void k_count_deg(const int* __restrict__ dst) {
    int e = blockIdx.x * blockDim.x + threadIdx.x;
    if (e < EE) atomicAdd(&g_deg[dst[e]], 1);
}
__global__ void k_scan_deg() {
    __shared__ int partial[256];
    int t = threadIdx.x;
    const int CH = (NN + 255) / 256;
    int base = t * CH;
    int s = 0;
    for (int i = 0; i < CH; i++) {
        int idx = base + i;
        if (idx < NN) s += g_deg[idx];
    }
    partial[t] = s;
    __syncthreads();
    if (t == 0) {
        int run = 0;
        for (int i = 0; i < 256; i++) { int v = partial[i]; partial[i] = run; run += v; }
        g_rowptr[NN] = run;
    }
    __syncthreads();
    int run = partial[t];
    for (int i = 0; i < CH; i++) {
        int idx = base + i;
        if (idx < NN) {
            g_rowptr[idx] = run;
            g_cursor[idx] = run;
            int d = g_deg[idx];
            g_deginv[idx] = (d > 0) ? (1.0f / (float)d) : 0.0f;
            run += d;
        }
    }
}
__global__ void k_fill_csr(const int* __restrict__ src, const int* __restrict__ dst) {
    int e = blockIdx.x * blockDim.x + threadIdx.x;
    if (e < EE) {
        int p = atomicAdd(&g_cursor[dst[e]], 1);
        g_col[p] = src[e];
    }
}

// pack GRU weights -> [N,K] K-major bf16 hi/lo, u/c columns interleaved.
// packed col n: f=n>>1, orig col = (n&1) ? 2F+f : F+f. rows: [Wxs;Wxn;Whs;Whn] (full) or [Whs;Whn].
__global__ void k_pack_gru(const float* __restrict__ Wxs, const float* __restrict__ Wxn,
                           const float* __restrict__ Whs, const float* __restrict__ Whn,
                           const float* __restrict__ bx, const float* __restrict__ bh,
                           __nv_bfloat16* __restrict__ Wh, __nv_bfloat16* __restrict__ Wl,
                           float* __restrict__ bias, int full) {
    int K = full ? K_FULL : K_HALF;
    int j = blockIdx.x * blockDim.x + threadIdx.x;
    if (j >= NOUT * K) return;
    int n = j / K, k = j % K;
    int f = n >> 1;
    int col = (n & 1) ? (2 * FF + f) : (FF + f);
    int blk = k >> 8, r = k & (FF - 1);
    const float* srcW;
    if (full) srcW = (blk == 0) ? Wxs : (blk == 1) ? Wxn : (blk == 2) ? Whs : Whn;
    else      srcW = (blk == 0) ? Whs : Whn;
    float w = srcW[r * (3 * FF) + col];
    __nv_bfloat16 hi = __float2bfloat16_rn(w);
    Wh[j] = hi;
    Wl[j] = __float2bfloat16_rn(w - __bfloat162float(hi));
    if (k == 0) bias[n] = bx[col] + bh[col];
}
__global__ void k_pack_out(const float* __restrict__ W, const float* __restrict__ b,
                           __nv_bfloat16* __restrict__ Wh, __nv_bfloat16* __restrict__ Wl,
                           float* __restrict__ bias) {
    int j = blockIdx.x * blockDim.x + threadIdx.x;
    if (j >= FF * FF) return;
    int n = j / FF, k = j % FF;
    float w = W[k * FF + n];
    __nv_bfloat16 hi = __float2bfloat16_rn(w);
    Wh[j] = hi;
    Wl[j] = __float2bfloat16_rn(w - __bfloat162float(hi));
    if (k == 0) bias[n] = b[n];
}

// ---------------- aggregation ----------------
__device__ __forceinline__ float4 f4add(float4 a, float4 b) {
    return make_float4(a.x + b.x, a.y + b.y, a.z + b.z, a.w + b.w);
}
__device__ __forceinline__ float4 f4scale(float4 a, float s) {
    return make_float4(a.x * s, a.y * s, a.z * s, a.w * s);
}
__global__ void k_agg_full(const float* __restrict__ x, const float* __restrict__ h) {
    int node = blockIdx.x;
    int t = threadIdx.x;  // 64
    int beg = g_rowptr[node], end = g_rowptr[node + 1];
    float4 sx = make_float4(0, 0, 0, 0), sh = sx;
    for (int j = beg; j < end; j++) {
        int s = g_col[j];
        sx = f4add(sx, *(const float4*)&x[(size_t)s * FF + t * 4]);
        sh = f4add(sh, *(const float4*)&h[(size_t)s * FF + t * 4]);
    }
    float di = g_deginv[node];
    size_t base = (size_t)node * K_FULL;
    *(float4*)&g_in[base + t * 4]        = *(const float4*)&x[(size_t)node * FF + t * 4];
    *(float4*)&g_in[base + 256 + t * 4]  = f4scale(sx, di);
    *(float4*)&g_in[base + 512 + t * 4]  = *(const float4*)&h[(size_t)node * FF + t * 4];
    *(float4*)&g_in[base + 768 + t * 4]  = f4scale(sh, di);
}
__global__ void k_agg_half(const float* __restrict__ h) {
    int node = blockIdx.x;
    int t = threadIdx.x;
    int beg = g_rowptr[node], end = g_rowptr[node + 1];
    float4 sh = make_float4(0, 0, 0, 0);
    for (int j = beg; j < end; j++)
        sh = f4add(sh, *(const float4*)&h[(size_t)g_col[j] * FF + t * 4]);
    size_t base = (size_t)node * K_HALF;
    *(float4*)&g_in[base + t * 4]       = *(const float4*)&h[(size_t)node * FF + t * 4];
    *(float4*)&g_in[base + 256 + t * 4] = f4scale(sh, g_deginv[node]);
}

// ---------------- mma.sync bf16-split GEMM ----------------
// C[M,N] = A[M,K] (fp32, split on the fly) @ W[K,N] (pre-split bf16 hi/lo, stored [N,K])
// 3 passes: Ah*Bh + Al*Bh + Ah*Bl.
// mode 0: fused GRU epilogue (u/c interleaved), Hout = hidden [NN,FF]
// mode 1: bias epilogue, Hout = output rows [NN,FF]
#define BM 128
#define BN 128
#define BK 32
#define PAD 40                              // halfs per smem row (80B, conflict-free ldmatrix)
#define AS_H 0
#define AS_L (128 * PAD)
#define WS_H (2 * 128 * PAD)
#define WS_L (3 * 128 * PAD)
#define STAGE_HALFS (4 * 128 * PAD)
#define SMEM_BYTES (2 * STAGE_HALFS * 2)

__global__ __launch_bounds__(256, 1) void k_mma_gemm(
    const float* __restrict__ A, int K,
    const __nv_bfloat16* __restrict__ Wh, const __nv_bfloat16* __restrict__ Wl,
    const float* __restrict__ bias,
    float* __restrict__ Hout, int mode) {
    extern __shared__ __align__(16) __nv_bfloat16 smem[];
    const uint32_t sbase = smem_u32(smem);

    const int tid = threadIdx.x;
    const int lane = tid & 31;
    const int wid = tid >> 5;
    const int wm = wid & 1;        // 0/1 -> 64-row half
    const int wn = wid >> 1;       // 0..3 -> 32-col quarter
    const int bm = blockIdx.y * BM;
    const int bn = blockIdx.x * BN;

    // loader indexing: 2 threads per row, 16 cols each
    const int lr = tid >> 1;
    const int lc = (tid & 1) * 16;
    int gmld = bm + lr; if (gmld >= NN) gmld = NN - 1;
    const float* arow = A + (size_t)gmld * K;
    const __nv_bfloat16* whrow = Wh + (size_t)(bn + lr) * K;
    const __nv_bfloat16* wlrow = Wl + (size_t)(bn + lr) * K;

    float aR[16];
    uint4 whR[2], wlR[2];

    auto gload = [&](int c) {
        int k0 = c * BK;
#pragma unroll
        for (int j = 0; j < 4; j++) {
            float4 v = *(const float4*)(arow + k0 + lc + j * 4);
            aR[j * 4 + 0] = v.x; aR[j * 4 + 1] = v.y;
            aR[j * 4 + 2] = v.z; aR[j * 4 + 3] = v.w;
        }
        whR[0] = *(const uint4*)(whrow + k0 + lc);
        whR[1] = *(const uint4*)(whrow + k0 + lc + 8);
        wlR[0] = *(const uint4*)(wlrow + k0 + lc);
        wlR[1] = *(const uint4*)(wlrow + k0 + lc + 8);
    };
    auto sstore = [&](int s) {
        __nv_bfloat16* st = smem + s * STAGE_HALFS;
#pragma unroll
        for (int j = 0; j < 2; j++) {
            uint32_t hw[4], lw[4];
#pragma unroll
            for (int q = 0; q < 4; q++) {
                float v0 = aR[j * 8 + q * 2], v1 = aR[j * 8 + q * 2 + 1];
                __nv_bfloat16 h0 = __float2bfloat16_rn(v0);
                __nv_bfloat16 h1 = __float2bfloat16_rn(v1);
                hw[q] = (uint32_t)__bfloat16_as_ushort(h0) |
                        ((uint32_t)__bfloat16_as_ushort(h1) << 16);
                lw[q] = pack_bf16_hi(v0 - __bfloat162float(h0), v1 - __bfloat162float(h1));
            }
            *(uint4*)(st + AS_H + lr * PAD + lc + j * 8) = make_uint4(hw[0], hw[1], hw[2], hw[3]);
            *(uint4*)(st + AS_L + lr * PAD + lc + j * 8) = make_uint4(lw[0], lw[1], lw[2], lw[3]);
        }
        *(uint4*)(st + WS_H + lr * PAD + lc)     = whR[0];
        *(uint4*)(st + WS_H + lr * PAD + lc + 8) = whR[1];
        *(uint4*)(st + WS_L + lr * PAD + lc)     = wlR[0];
        *(uint4*)(st + WS_L + lr * PAD + lc + 8) = wlR[1];
    };

    // ldmatrix per-lane address components
    const int aRowL = (lane & 15);
    const int aSeg  = (lane >> 4) * 8;
    const int bIdx  = lane & 15;
    const int bRowL = bIdx & 7;
    const int bSeg  = (bIdx >> 3) * 8;

    float acc[4][4][4];
#pragma unroll
    for (int i = 0; i < 4; i++)
#pragma unroll
        for (int j = 0; j < 4; j++)
#pragma unroll
            for (int q = 0; q < 4; q++) acc[i][j][q] = 0.0f;

    auto compute = [&](int s) {
        uint32_t base = sbase + s * STAGE_HALFS * 2;
#pragma unroll
        for (int kk = 0; kk < 2; kk++) {
            uint32_t ah[4][4], al[4][4];
#pragma unroll
            for (int i = 0; i < 4; i++) {
                uint32_t off = ((wm * 64 + i * 16 + aRowL) * PAD + kk * 16 + aSeg) * 2;
                ldsm_x4(ah[i], base + AS_H * 2 + off);
                ldsm_x4(al[i], base + AS_L * 2 + off);
            }
            uint32_t bh[4][2], bl[4][2];
#pragma unroll
            for (int j = 0; j < 4; j++) {
                uint32_t off = ((wn * 32 + j * 8 + bRowL) * PAD + kk * 16 + bSeg) * 2;
                ldsm_x2(bh[j], base + WS_H * 2 + off);
                ldsm_x2(bl[j], base + WS_L * 2 + off);
            }
#pragma unroll
            for (int i = 0; i < 4; i++)
#pragma unroll
                for (int j = 0; j < 4; j++) {
                    mma_bf16(acc[i][j], ah[i], bh[j]);
                    mma_bf16(acc[i][j], al[i], bh[j]);
                    mma_bf16(acc[i][j], ah[i], bl[j]);
                }
        }
    };

    const int NC = K / BK;
    gload(0);
    sstore(0);
    __syncthreads();
    for (int c = 0; c < NC; c++) {
        if (c + 1 < NC) gload(c + 1);
        compute(c & 1);
        __syncthreads();
        if (c + 1 < NC) {
            sstore((c + 1) & 1);
            __syncthreads();
        }
    }

    // ---------------- epilogue ----------------
#pragma unroll
    for (int i = 0; i < 4; i++) {
        int r0 = bm + wm * 64 + i * 16 + (lane >> 2);
#pragma unroll
        for (int j = 0; j < 4; j++) {
            int col = wn * 32 + j * 8 + (lane & 3) * 2;    // even
            int gcol = bn + col;
            float b0 = __ldg(&bias[gcol]);
            float b1 = __ldg(&bias[gcol + 1]);
            if (mode == 0) {
                int f = gcol >> 1;
#pragma unroll
                for (int half = 0; half < 2; half++) {
                    int gm = r0 + half * 8;
                    if (gm < NN) {
                        float zu = acc[i][j][half * 2]     + b0;
                        float zc = acc[i][j][half * 2 + 1] + b1;
                        float u = 1.0f / (1.0f + __expf(-zu));
                        float cc = tanhf(zc);
                        float hv = Hout[(size_t)gm * FF + f];
                        Hout[(size_t)gm * FF + f] = u * hv + (1.0f - u) * cc;
                    }
                }
            } else {
#pragma unroll
                for (int half = 0; half < 2; half++) {
                    int gm = r0 + half * 8;
                    if (gm < NN) {
                        float2 v;
                        v.x = acc[i][j][half * 2]     + b0;
                        v.y = acc[i][j][half * 2 + 1] + b1;
                        *(float2*)&Hout[(size_t)gm * FF + gcol] = v;
                    }
                }
            }
        }
    }
}

// ---------------- host orchestration ----------------
extern "C" void kernel_launch(void* const* d_in, const int* in_sizes, int n_in,
                              void* d_out, int out_size) {
    const float* x    = (const float*)d_in[0];
    const int*   src  = (const int*)d_in[1];
    const int*   dst  = (const int*)d_in[2];
    const float* eWxs = (const float*)d_in[3];
    const float* eWxn = (const float*)d_in[4];
    const float* ebx  = (const float*)d_in[5];
    const float* eWhs = (const float*)d_in[6];
    const float* eWhn = (const float*)d_in[7];
    const float* ebh  = (const float*)d_in[8];
    const float* dWxs = (const float*)d_in[9];
    const float* dWxn = (const float*)d_in[10];
    const float* dbx  = (const float*)d_in[11];
    const float* dWhs = (const float*)d_in[12];
    const float* dWhn = (const float*)d_in[13];
    const float* dbh  = (const float*)d_in[14];
    const float* outW = (const float*)d_in[15];
    const float* outB = (const float*)d_in[16];
    float* out = (float*)d_out;

    float *p_in, *p_h0, *p_h1, *p_bias;
    __nv_bfloat16 *p_Wh, *p_Wl;
    int* p_deg;
    cudaGetSymbolAddress((void**)&p_in, g_in);
    cudaGetSymbolAddress((void**)&p_h0, g_h0);
    cudaGetSymbolAddress((void**)&p_h1, g_h1);
    cudaGetSymbolAddress((void**)&p_Wh, g_Wh);
    cudaGetSymbolAddress((void**)&p_Wl, g_Wl);
    cudaGetSymbolAddress((void**)&p_bias, g_bias);
    cudaGetSymbolAddress((void**)&p_deg, g_deg);

    cudaFuncSetAttribute(k_mma_gemm, cudaFuncAttributeMaxDynamicSharedMemorySize, SMEM_BYTES);

    const int WLF = FF * 3 * FF;
    const int BLF = 3 * FF;

    // graph structure
    k_zero_int<<<(NN + 255) / 256, 256>>>(p_deg, NN);
    k_count_deg<<<(EE + 255) / 256, 256>>>(dst);
    k_scan_deg<<<1, 256>>>();
    k_fill_csr<<<(EE + 255) / 256, 256>>>(src, dst);

    // zero hidden
    k_zero_f<<<(NN * FF + 255) / 256, 256>>>(p_h0, NN * FF);
    k_zero_f<<<(NN * FF + 255) / 256, 256>>>(p_h1, NN * FF);

    // pack + split weights
    {
        int nfull = NOUT * K_FULL, nhalf = NOUT * K_HALF;
        k_pack_gru<<<(nfull + 255) / 256, 256>>>(eWxs, eWxn, eWhs, eWhn, ebx, ebh,
                                                 p_Wh + W_ENC0, p_Wl + W_ENC0, p_bias + 0 * NOUT, 1);
        k_pack_gru<<<(nfull + 255) / 256, 256>>>(eWxs + WLF, eWxn + WLF, eWhs + WLF, eWhn + WLF,
                                                 ebx + BLF, ebh + BLF,
                                                 p_Wh + W_ENC1, p_Wl + W_ENC1, p_bias + 1 * NOUT, 1);
        k_pack_gru<<<(nhalf + 255) / 256, 256>>>(dWxs, dWxn, dWhs, dWhn, dbx, dbh,
                                                 p_Wh + W_DEC0, p_Wl + W_DEC0, p_bias + 2 * NOUT, 0);
        k_pack_gru<<<(nfull + 255) / 256, 256>>>(dWxs + WLF, dWxn + WLF, dWhs + WLF, dWhn + WLF,
                                                 dbx + BLF, dbh + BLF,
                                                 p_Wh + W_DEC1, p_Wl + W_DEC1, p_bias + 3 * NOUT, 1);
        k_pack_out<<<(FF * FF + 255) / 256, 256>>>(outW, outB, p_Wh + W_OUTP, p_Wl + W_OUTP,
                                                   p_bias + 4 * NOUT);
    }

    dim3 grid_pre(NOUT / BN, (NN + BM - 1) / BM);   // (4, 79)
    dim3 grid_out(FF / BN, (NN + BM - 1) / BM);     // (2, 79)

    // encoder
    for (int t = 0; t < TT; t++) {
        k_agg_full<<<NN, 64>>>(x + (size_t)t * NN * FF, p_h0);
        k_mma_gemm<<<grid_pre, 256, SMEM_BYTES>>>(p_in, K_FULL,
                                                  p_Wh + W_ENC0, p_Wl + W_ENC0,
                                                  p_bias + 0 * NOUT, p_h0, 0);
        k_agg_full<<<NN, 64>>>(p_h0, p_h1);
        k_mma_gemm<<<grid_pre, 256, SMEM_BYTES>>>(p_in, K_FULL,
                                                  p_Wh + W_ENC1, p_Wl + W_ENC1,
                                                  p_bias + 1 * NOUT, p_h1, 0);
    }
    // decoder
    for (int t = 0; t < TT; t++) {
        k_agg_half<<<NN, 64>>>(p_h0);
        k_mma_gemm<<<grid_pre, 256, SMEM_BYTES>>>(p_in, K_HALF,
                                                  p_Wh + W_DEC0, p_Wl + W_DEC0,
                                                  p_bias + 2 * NOUT, p_h0, 0);
        k_agg_full<<<NN, 64>>>(p_h0, p_h1);
        k_mma_gemm<<<grid_pre, 256, SMEM_BYTES>>>(p_in, K_FULL,
                                                  p_Wh + W_DEC1, p_Wl + W_DEC1,
                                                  p_bias + 3 * NOUT, p_h1, 0);
        k_mma_gemm<<<grid_out, 256, SMEM_BYTES>>>(p_h1, FF,
                                                  p_Wh + W_OUTP, p_Wl + W_OUTP,
                                                  p_bias + 4 * NOUT, out + (size_t)t * NN * FF, 1);
    }
    (void)in_sizes; (void)n_in; (void)out_size;
}